// round 5
// baseline (speedup 1.0000x reference)
#include <cuda_runtime.h>
#include <cstdint>

#define NB   16
#define NN   20000
#define NE   640000
#define NREG 2000
#define DIN  128
#define FF   32

// ---------------- scratch (device globals; no allocation allowed) ----------
__device__ float    g_h[(size_t)NB * NN * FF];       // 40.96 MB
__device__ float    g_hsrc[(size_t)NB * NREG * FF];  // 4.1 MB (hot gather set)
__device__ float    g_rep[(size_t)NB * NN * FF];     // 40.96 MB
__device__ float    g_asrc[NB * NN];
__device__ float    g_adst[NB * NN];
__device__ int      g_src32[NE];
__device__ int      g_dst32[NE];
__device__ int      g_cnt[NN];
__device__ int      g_off[NN + 1];
__device__ int      g_cur[NN];
__device__ unsigned g_sorted[NE];                    // (src<<20)|eid
__device__ int      g_soff[NREG + 1];
__device__ float    g_meanpart[NB][8];
__device__ float    g_mean[NB];
__device__ float    g_c;
__device__ int      g_is64;

// ---------------- f32x2 helpers ---------------------------------------------
__device__ __forceinline__ void fma2(unsigned long long& d,
                                     unsigned long long a,
                                     unsigned long long b) {
    asm("fma.rn.f32x2 %0, %1, %2, %0;" : "+l"(d) : "l"(a), "l"(b));
}
__device__ __forceinline__ unsigned long long dup2(float w) {
    unsigned long long r;
    asm("mov.b64 %0, {%1, %1};" : "=l"(r) : "f"(w));
    return r;
}
__device__ __forceinline__ void unpack2(unsigned long long v, float& lo, float& hi) {
    asm("mov.b64 {%0, %1}, %2;" : "=f"(lo), "=f"(hi) : "l"(v));
}

// ---------------- dtype detection -------------------------------------------
__global__ void k_detect(const int* __restrict__ p) {
    int any = 0;
    for (int i = threadIdx.x; i < 1024; i += 32)
        if ((i & 1) && p[i] != 0) any = 1;
    #pragma unroll
    for (int o = 16; o; o >>= 1) any |= __shfl_xor_sync(0xFFFFFFFFu, any, o);
    if (threadIdx.x == 0) g_is64 = !any;
}

// ---------------- prep: zero cnt, mean partials, scalar c -------------------
__global__ void k_prep(const float* __restrict__ eattr,
                       const float* __restrict__ lin_edge,
                       const float* __restrict__ att_edge) {
    int tid = threadIdx.x, bx = blockIdx.x, by = blockIdx.y;
    int lane = tid & 31, wid = tid >> 5;

    int id = (by * 8 + bx) * 256 + tid;
    if (id < NN) g_cnt[id] = 0;

    if (bx == 0 && by == 0 && wid == 1) {
        float p = lin_edge[lane] * att_edge[lane];
        #pragma unroll
        for (int o = 16; o; o >>= 1) p += __shfl_xor_sync(0xFFFFFFFFu, p, o);
        if (lane == 0) g_c = p;
    }

    const float* p = eattr + (size_t)by * NE;
    float s = 0.f;
    for (int i = bx * 256 + tid; i < NE; i += 8 * 256) s += p[i];
    __shared__ float sm[8];
    #pragma unroll
    for (int o = 16; o; o >>= 1) s += __shfl_xor_sync(0xFFFFFFFFu, s, o);
    if (lane == 0) sm[wid] = s;
    __syncthreads();
    if (wid == 0) {
        s = (lane < 8) ? sm[lane] : 0.f;
        #pragma unroll
        for (int o = 4; o; o >>= 1) s += __shfl_xor_sync(0xFFFFFFFFu, s, o);
        if (lane == 0) g_meanpart[by][bx] = s;
    }
}

// ---------------- convert indices + histogram -------------------------------
__global__ void k_convert(const void* __restrict__ srcv,
                          const void* __restrict__ dstv) {
    int e = blockIdx.x * blockDim.x + threadIdx.x;
    if (e >= NE) return;
    int s, d;
    if (g_is64) {
        s = (int)((const long long*)srcv)[e];
        d = (int)((const long long*)dstv)[e];
    } else {
        s = ((const int*)srcv)[e];
        d = ((const int*)dstv)[e];
    }
    g_src32[e] = s;
    g_dst32[e] = d;
    atomicAdd(&g_cnt[d], 1);
}

// ---------------- scan + soff + mean finalize (single block, 1024 thr) ------
__global__ void k_scan() {
    __shared__ int tot[1024];
    int t = threadIdx.x;
    int base = t * 20;
    int loc[20];
    int run = 0;
    #pragma unroll
    for (int i = 0; i < 20; i++) {
        int idx = base + i;
        int v = (idx < NN) ? g_cnt[idx] : 0;
        loc[i] = run;
        run += v;
    }
    tot[t] = run;
    __syncthreads();
    for (int off = 1; off < 1024; off <<= 1) {
        int v = (t >= off) ? tot[t - off] : 0;
        __syncthreads();
        tot[t] += v;
        __syncthreads();
    }
    int excl = tot[t] - run;
    #pragma unroll
    for (int i = 0; i < 20; i++) {
        int idx = base + i;
        if (idx < NN) {
            int o = excl + loc[i];
            g_off[idx] = o;
            g_cur[idx] = o;
        }
    }
    if (t == 1023) g_off[NN] = tot[1023];

    for (int r = t; r <= NREG; r += 1024) {
        int lo = 0, hi = NE;
        while (lo < hi) {
            int mid = (lo + hi) >> 1;
            if (g_src32[mid] < r) lo = mid + 1; else hi = mid;
        }
        g_soff[r] = lo;
    }

    if (t < NB) {
        float s = 0.f;
        #pragma unroll
        for (int i = 0; i < 8; i++) s += g_meanpart[t][i];
        g_mean[t] = s * (1.0f / NE);
    }
}

__global__ void k_scatter() {
    int e = blockIdx.x * blockDim.x + threadIdx.x;
    if (e >= NE) return;
    int d = g_dst32[e];
    int pos = atomicAdd(&g_cur[d], 1);
    g_sorted[pos] = ((unsigned)g_src32[e] << 20) | (unsigned)e;
}

// ---------------- GEMM (f32x2 packed): h = x @ W, a_src, a_dst, hsrc copy ---
__global__ void __launch_bounds__(256)
k_gemm(const float* __restrict__ x, const float* __restrict__ W,
       const float* __restrict__ attS, const float* __restrict__ attD) {
    __shared__ float  Wt[32 * 132];
    __shared__ float2 xp[8][4][128];

    int tid = threadIdx.x, wid = tid >> 5, lane = tid & 31;

    for (int i = tid; i < DIN * FF; i += 256) {
        int k = i >> 5, f = i & 31;
        Wt[f * 132 + k] = W[i];
    }

    size_t rowBase = (size_t)blockIdx.x * 64 + (size_t)wid * 8;
    const float* xg = x + rowBase * DIN;
    #pragma unroll
    for (int p = 0; p < 4; p++) {
        float4 r0 = ((const float4*)(xg + (2 * p + 0) * DIN))[lane];
        float4 r1 = ((const float4*)(xg + (2 * p + 1) * DIN))[lane];
        xp[wid][p][4 * lane + 0] = make_float2(r0.x, r1.x);
        xp[wid][p][4 * lane + 1] = make_float2(r0.y, r1.y);
        xp[wid][p][4 * lane + 2] = make_float2(r0.z, r1.z);
        xp[wid][p][4 * lane + 3] = make_float2(r0.w, r1.w);
    }
    __syncthreads();

    unsigned long long acc[4] = {0ull, 0ull, 0ull, 0ull};
    #pragma unroll 4
    for (int kc = 0; kc < 32; kc++) {
        float4 wf = *(const float4*)&Wt[lane * 132 + kc * 4];
        unsigned long long w0 = dup2(wf.x), w1 = dup2(wf.y);
        unsigned long long w2 = dup2(wf.z), w3 = dup2(wf.w);
        #pragma unroll
        for (int p = 0; p < 4; p++) {
            ulonglong2 u01 = *(const ulonglong2*)&xp[wid][p][4 * kc + 0];
            ulonglong2 u23 = *(const ulonglong2*)&xp[wid][p][4 * kc + 2];
            fma2(acc[p], u01.x, w0);
            fma2(acc[p], u01.y, w1);
            fma2(acc[p], u23.x, w2);
            fma2(acc[p], u23.y, w3);
        }
    }

    float aS = attS[lane], aD = attD[lane];
    float* hp = g_h + rowBase * FF;
    #pragma unroll
    for (int p = 0; p < 4; p++) {
        float lo, hi;
        unpack2(acc[p], lo, hi);
        size_t grow0 = rowBase + 2 * p, grow1 = grow0 + 1;
        hp[(2 * p + 0) * FF + lane] = lo;
        hp[(2 * p + 1) * FF + lane] = hi;
        // compact copy of src-node rows (n < NREG) for L1-resident gathers
        {
            int b0 = (int)(grow0 / NN), n0 = (int)(grow0 - (size_t)b0 * NN);
            if (n0 < NREG) g_hsrc[((size_t)b0 * NREG + n0) * FF + lane] = lo;
            int b1 = (int)(grow1 / NN), n1 = (int)(grow1 - (size_t)b1 * NN);
            if (n1 < NREG) g_hsrc[((size_t)b1 * NREG + n1) * FF + lane] = hi;
        }
        float vs0 = lo * aS, vd0 = lo * aD, vs1 = hi * aS, vd1 = hi * aD;
        #pragma unroll
        for (int o = 16; o; o >>= 1) {
            vs0 += __shfl_xor_sync(0xFFFFFFFFu, vs0, o);
            vd0 += __shfl_xor_sync(0xFFFFFFFFu, vd0, o);
            vs1 += __shfl_xor_sync(0xFFFFFFFFu, vs1, o);
            vd1 += __shfl_xor_sync(0xFFFFFFFFu, vd1, o);
        }
        if (lane == 0) {
            g_asrc[grow0] = vs0;
            g_adst[grow0] = vd0;
            g_asrc[grow1] = vs1;
            g_adst[grow1] = vd1;
        }
    }
}

// ---------------- single-pass per-(b,dst) softmax + aggregation -------------
__device__ __forceinline__ float lrelu(float a) {
    return fmaxf(a, 0.f) + 0.2f * fminf(a, 0.f);
}

__global__ void __launch_bounds__(256)
k_edge(const float* __restrict__ eattr, const float* __restrict__ bias) {
    int wid = threadIdx.x >> 5, lane = threadIdx.x & 31;
    int seg = blockIdx.x * 8 + wid;                 // 0 .. NB*NN-1
    int b = seg / NN, d = seg - b * NN;

    const float* asb = g_asrc + b * NN;
    const float* eab = eattr + (size_t)b * NE;
    const float* hsb = g_hsrc + (size_t)b * NREG * FF;   // hot 256KB/batch
    float ad = g_adst[b * NN + d];
    float c = g_c;
    int lo = g_off[d], hi = g_off[d + 1];
    int q = lane & 7, g4 = lane >> 3;

    float4 acc = make_float4(0.f, 0.f, 0.f, 0.f);
    float ssum = 0.f;

    for (int base = lo; base < hi; base += 32) {
        int m = hi - base;
        if (m > 32) m = 32;
        float ex = 0.f;
        int idx = 0;                                 // safe row, weight 0
        if (lane < m) {
            unsigned p = __ldcs(&g_sorted[base + lane]);
            int sA = p >> 20;
            int eid = p & 0xFFFFFu;
            ex = __expf(lrelu(asb[sA] + ad + c * __ldcs(&eab[eid])));
            idx = sA * FF;
        }
        ssum += ex;
        for (int g = 0; g < m; g += 8) {
            int j0 = g + g4, j1 = g + 4 + g4;
            float e0 = __shfl_sync(0xFFFFFFFFu, ex, j0);
            int   i0 = __shfl_sync(0xFFFFFFFFu, idx, j0);
            float e1 = __shfl_sync(0xFFFFFFFFu, ex, j1);
            int   i1 = __shfl_sync(0xFFFFFFFFu, idx, j1);
            float4 v0 = *(const float4*)(hsb + i0 + q * 4);
            float4 v1 = *(const float4*)(hsb + i1 + q * 4);
            acc.x = fmaf(e0, v0.x, acc.x);
            acc.y = fmaf(e0, v0.y, acc.y);
            acc.z = fmaf(e0, v0.z, acc.z);
            acc.w = fmaf(e0, v0.w, acc.w);
            acc.x = fmaf(e1, v1.x, acc.x);
            acc.y = fmaf(e1, v1.y, acc.y);
            acc.z = fmaf(e1, v1.z, acc.z);
            acc.w = fmaf(e1, v1.w, acc.w);
        }
    }

    float exs = __expf(lrelu(asb[d] + ad + c * g_mean[b]));
    #pragma unroll
    for (int o = 16; o; o >>= 1) ssum += __shfl_xor_sync(0xFFFFFFFFu, ssum, o);
    float inv = 1.f / (ssum + exs);

    #pragma unroll
    for (int o = 8; o <= 16; o <<= 1) {
        acc.x += __shfl_xor_sync(0xFFFFFFFFu, acc.x, o);
        acc.y += __shfl_xor_sync(0xFFFFFFFFu, acc.y, o);
        acc.z += __shfl_xor_sync(0xFFFFFFFFu, acc.z, o);
        acc.w += __shfl_xor_sync(0xFFFFFFFFu, acc.w, o);
    }

    if (lane < 8) {
        const float4* hsp = (const float4*)(g_h + ((size_t)b * NN + d) * FF + q * 4);
        float4 hs = __ldcs(hsp);                     // self row, read once
        float4 bq = *(const float4*)(bias + q * 4);
        float4 r;
        r.x = fmaf(exs, hs.x, acc.x) * inv + bq.x;
        r.y = fmaf(exs, hs.y, acc.y) * inv + bq.y;
        r.z = fmaf(exs, hs.z, acc.z) * inv + bq.z;
        r.w = fmaf(exs, hs.w, acc.w) * inv + bq.w;
        *(float4*)(g_rep + ((size_t)b * NN + d) * FF + q * 4) = r;
    }
}

// ---------------- regulon pooling: out[b,r] = rep[b,r] + sum rep[b,dst] -----
__global__ void __launch_bounds__(256)
k_pool(float* __restrict__ out) {
    int wid = threadIdx.x >> 5, lane = threadIdx.x & 31;
    int seg = blockIdx.x * 8 + wid;                 // 0 .. NB*NREG-1
    int b = seg / NREG, r = seg - b * NREG;
    int lo = g_soff[r], hi = g_soff[r + 1];
    const float* repb = g_rep + (size_t)b * NN * FF;
    int q = lane & 7, g4 = lane >> 3;

    float4 a0 = make_float4(0.f, 0.f, 0.f, 0.f);
    float4 a1 = make_float4(0.f, 0.f, 0.f, 0.f);

    for (int base = lo; base < hi; base += 32) {
        int m = hi - base;
        if (m > 32) m = 32;
        int idx = (lane < m) ? __ldcs(&g_dst32[base + lane]) * FF : -1;
        for (int g = 0; g < m; g += 8) {
            int i0 = __shfl_sync(0xFFFFFFFFu, idx, g + g4);
            int i1 = __shfl_sync(0xFFFFFFFFu, idx, g + 4 + g4);
            if (i0 >= 0) {
                float4 v = *(const float4*)(repb + i0 + q * 4);
                a0.x += v.x; a0.y += v.y; a0.z += v.z; a0.w += v.w;
            }
            if (i1 >= 0) {
                float4 v = *(const float4*)(repb + i1 + q * 4);
                a1.x += v.x; a1.y += v.y; a1.z += v.z; a1.w += v.w;
            }
        }
    }
    a0.x += a1.x; a0.y += a1.y; a0.z += a1.z; a0.w += a1.w;

    #pragma unroll
    for (int o = 8; o <= 16; o <<= 1) {
        a0.x += __shfl_xor_sync(0xFFFFFFFFu, a0.x, o);
        a0.y += __shfl_xor_sync(0xFFFFFFFFu, a0.y, o);
        a0.z += __shfl_xor_sync(0xFFFFFFFFu, a0.z, o);
        a0.w += __shfl_xor_sync(0xFFFFFFFFu, a0.w, o);
    }

    if (lane < 8) {
        float4 self = *(const float4*)(repb + (size_t)r * FF + q * 4);
        float4 o4;
        o4.x = a0.x + self.x;
        o4.y = a0.y + self.y;
        o4.z = a0.z + self.z;
        o4.w = a0.w + self.w;
        *(float4*)(out + ((size_t)b * NREG + r) * FF + q * 4) = o4;
    }
}

// ---------------- launch ---------------------------------------------------
extern "C" void kernel_launch(void* const* d_in, const int* in_sizes, int n_in,
                              void* d_out, int out_size) {
    const float* x        = (const float*)d_in[0];
    const float* edgeattr = (const float*)d_in[1];
    const float* W        = (const float*)d_in[2];
    const float* att_src  = (const float*)d_in[3];
    const float* att_dst  = (const float*)d_in[4];
    const float* lin_edge = (const float*)d_in[5];
    const float* att_edge = (const float*)d_in[6];
    const float* bias     = (const float*)d_in[7];
    const void*  esrc     = d_in[8];
    const void*  edst     = d_in[9];
    float* out = (float*)d_out;

    k_detect<<<1, 32>>>((const int*)edst);
    k_prep<<<dim3(8, NB), 256>>>(edgeattr, lin_edge, att_edge);
    k_convert<<<NE / 256, 256>>>(esrc, edst);
    k_gemm<<<(NB * NN) / 64, 256>>>(x, W, att_src, att_dst);  // profiled slot
    k_scan<<<1, 1024>>>();
    k_scatter<<<NE / 256, 256>>>();
    k_edge<<<(NB * NN) / 8, 256>>>(edgeattr, bias);
    k_pool<<<(NB * NREG) / 8, 256>>>(out);
}